// round 4
// baseline (speedup 1.0000x reference)
#include <cuda_runtime.h>

#define NC 62
#define HW_BITS 18
#define HW (1 << HW_BITS)
#define NP (8 * HW)              // 2,097,152 pixels
#define NTHREADS 256
#define NBLOCKS 2048
#define WARPS_TOTAL (NBLOCKS * (NTHREADS / 32))  // 16384
#define PIX_PER_WARP_ITER 32
#define ITERS (NP / (WARPS_TOTAL * PIX_PER_WARP_ITER))  // exactly 4
#define IGN 255
#define SMOOTH 1e-6f
#define PAD 32

__device__ float g_acc[NC * PAD];
__device__ float g_inter[NC * PAD];
__device__ float g_tgt[NC * PAD];
__device__ unsigned int g_count;

__global__ __launch_bounds__(NTHREADS, 2) void dice_kernel(
    const float* __restrict__ pred, const int* __restrict__ target,
    float* __restrict__ out) {
    __shared__ float s_acc[NC];
    __shared__ float s_inter[NC];
    __shared__ float s_tgt[NC];
    __shared__ bool s_last;

    int tid = threadIdx.x;
    int lane = tid & 31;
    int h = lane & 3;        // channel chunk: channels [h*16, h*16+16)
    int q = lane >> 2;       // pixel-quad index within warp (0..7)
    int warp_g = blockIdx.x * (NTHREADS / 32) + (tid >> 5);

    if (tid < NC) {
        s_acc[tid] = 0.0f;
        s_inter[tid] = 0.0f;
        s_tgt[tid] = 0.0f;
    }
    __syncthreads();

    float acc[16];
#pragma unroll
    for (int j = 0; j < 16; j++) acc[j] = 0.0f;

#pragma unroll 1
    for (int it = 0; it < ITERS; it++) {
        int p = (warp_g + it * WARPS_TOTAL) * PIX_PER_WARP_ITER + q * 4;
        int n = p >> HW_BITS;
        int hw = p & (HW - 1);

        int4 t4 = *(const int4*)(target + p);  // 4 pixels' labels (bcast in quad)

        const float4* b4 = (const float4*)(pred +
            (((size_t)(n * NC + h * 16)) << HW_BITS) + (size_t)hw);

        // Phase A: 16 front-batched LDG.128 (full-line wavefronts: 8 q-lanes
        // x 16B = 128B contiguous per channel per instruction)
        float4 v[16];
#pragma unroll
        for (int j = 0; j < 16; j++) {
            if (h * 16 + j < NC) v[j] = b4[(size_t)j << (HW_BITS - 2)];
            else v[j] = make_float4(0.f, 0.f, 0.f, 0.f);
        }

        // Phase B: exp in place + per-pixel partial Z (4 pixels)
        float zx = 0.f, zy = 0.f, zz = 0.f, zw = 0.f;
#pragma unroll
        for (int j = 0; j < 16; j++) {
            bool cv = (h * 16 + j < NC);
            float ex = cv ? __expf(v[j].x) : 0.f;
            float ey = cv ? __expf(v[j].y) : 0.f;
            float ez = cv ? __expf(v[j].z) : 0.f;
            float ew = cv ? __expf(v[j].w) : 0.f;
            v[j].x = ex; v[j].y = ey; v[j].z = ez; v[j].w = ew;
            zx += ex; zy += ey; zz += ez; zw += ew;
        }
        // combine Z across the 4 chunk-lanes of each quad
        zx += __shfl_xor_sync(0xffffffffu, zx, 1);
        zx += __shfl_xor_sync(0xffffffffu, zx, 2);
        zy += __shfl_xor_sync(0xffffffffu, zy, 1);
        zy += __shfl_xor_sync(0xffffffffu, zy, 2);
        zz += __shfl_xor_sync(0xffffffffu, zz, 1);
        zz += __shfl_xor_sync(0xffffffffu, zz, 2);
        zw += __shfl_xor_sync(0xffffffffu, zw, 1);
        zw += __shfl_xor_sync(0xffffffffu, zw, 2);

        float sx = (t4.x != IGN) ? __fdividef(1.f, zx) : 0.f;  // invZ * validf
        float sy = (t4.y != IGN) ? __fdividef(1.f, zy) : 0.f;
        float sz = (t4.z != IGN) ? __fdividef(1.f, zz) : 0.f;
        float sw = (t4.w != IGN) ? __fdividef(1.f, zw) : 0.f;

        // Phase C: per-class register accumulation (4 pixels)
#pragma unroll
        for (int j = 0; j < 16; j++) {
            acc[j] = fmaf(v[j].x, sx,
                     fmaf(v[j].y, sy,
                     fmaf(v[j].z, sz,
                     fmaf(v[j].w, sw, acc[j]))));
        }

        // Phase D: lane h owns pixel h of its quad.
        // Gather softmax[target] by reloading the logit (L1 hit: line is hot).
        int tmine = (h == 0) ? t4.x : (h == 1) ? t4.y : (h == 2) ? t4.z : t4.w;
        float smine = (h == 0) ? sx : (h == 1) ? sy : (h == 2) ? sz : sw;
        bool valid = (tmine != IGN);
        int tc = valid ? tmine : 0;
        float xt = __ldg(pred + (((size_t)(n * NC + tc)) << HW_BITS) +
                         (size_t)(hw + h));
        float gi = __expf(xt) * smine;  // 0 if invalid (smine==0)

        atomicAdd(&s_inter[tc], gi);
        atomicAdd(&s_tgt[tc], valid ? 1.0f : 0.0f);
    }

    // Reduce acc across the 8 lanes with the same chunk h, then to shared
#pragma unroll
    for (int j = 0; j < 16; j++) {
        float vv = acc[j];
        vv += __shfl_xor_sync(0xffffffffu, vv, 4);
        vv += __shfl_xor_sync(0xffffffffu, vv, 8);
        vv += __shfl_xor_sync(0xffffffffu, vv, 16);
        if (lane < 4) {
            int c = lane * 16 + j;
            if (c < NC) atomicAdd(&s_acc[c], vv);
        }
    }
    __syncthreads();

    // One global atomic per class per block (padded -> spread L2 slices)
    if (tid < NC) {
        atomicAdd(&g_acc[tid * PAD], s_acc[tid]);
        atomicAdd(&g_inter[tid * PAD], s_inter[tid]);
        atomicAdd(&g_tgt[tid * PAD], s_tgt[tid]);
    }
    __threadfence();
    __syncthreads();
    if (tid == 0) {
        unsigned prev = atomicAdd(&g_count, 1u);
        s_last = (prev == NBLOCKS - 1);
    }
    __syncthreads();
    if (!s_last) return;

    // ---- last block: finalize ----
    float dice = 0.0f, has = 0.0f;
    if (tid < NC) {
        float ps = atomicAdd(&g_acc[tid * PAD], 0.0f);
        float iv = atomicAdd(&g_inter[tid * PAD], 0.0f);
        float tg = atomicAdd(&g_tgt[tid * PAD], 0.0f);
        float un = ps + tg;
        if (un > 0.0f) {
            has = 1.0f;
            dice = (2.0f * iv + SMOOTH) / (un + SMOOTH);
        }
    }
    __shared__ float sd[8], sh[8];
#pragma unroll
    for (int o = 16; o > 0; o >>= 1) {
        dice += __shfl_xor_sync(0xffffffffu, dice, o);
        has += __shfl_xor_sync(0xffffffffu, has, o);
    }
    if (lane == 0) {
        sd[tid >> 5] = dice;
        sh[tid >> 5] = has;
    }
    __syncthreads();
    if (tid == 0) {
        float ds = 0.0f, hs = 0.0f;
#pragma unroll
        for (int w = 0; w < NTHREADS / 32; w++) {
            ds += sd[w];
            hs += sh[w];
        }
        float mean = (hs > 0.0f) ? (ds / fmaxf(hs, 1.0f)) : 1.0f;
        out[0] = 1.0f - mean;
    }
    __syncthreads();
    // reset globals so every graph replay starts clean
    if (tid < NC) {
        g_acc[tid * PAD] = 0.0f;
        g_inter[tid * PAD] = 0.0f;
        g_tgt[tid * PAD] = 0.0f;
    }
    if (tid == 0) g_count = 0;
}

extern "C" void kernel_launch(void* const* d_in, const int* in_sizes, int n_in,
                              void* d_out, int out_size) {
    const float* pred = (const float*)d_in[0];
    const int* target = (const int*)d_in[1];
    float* out = (float*)d_out;
    dice_kernel<<<NBLOCKS, NTHREADS>>>(pred, target, out);
}